// round 6
// baseline (speedup 1.0000x reference)
#include <cuda_runtime.h>
#include <math.h>

#define D_MODEL 32
#define NHEAD 4
#define WIN 256
#define DFF 64
#define INDIM 58
#define HOUT 25
#define NLAYER 4

// ---- shared memory: K/V only (+ w2T staged into dead K buffer during FF) ----
#define KV_STRIDE 36
#define OFF_K  0
#define OFF_V  (WIN*KV_STRIDE)            // 9216
#define SMEM_FLOATS (2*WIN*KV_STRIDE)     // 18432
#define SMEM_BYTES (SMEM_FLOATS * 4)      // 73728 -> 3 CTAs/SM

typedef unsigned long long u64;

__device__ __forceinline__ u64 pk2(float lo, float hi) {
    u64 r; asm("mov.b64 %0,{%1,%2};" : "=l"(r) : "f"(lo), "f"(hi)); return r;
}
__device__ __forceinline__ void upk2(u64 p, float& lo, float& hi) {
    asm("mov.b64 {%0,%1},%2;" : "=f"(lo), "=f"(hi) : "l"(p));
}
__device__ __forceinline__ u64 ffma2(u64 a, u64 b, u64 c) {
    u64 d; asm("fma.rn.f32x2 %0,%1,%2,%3;" : "=l"(d) : "l"(a), "l"(b), "l"(c)); return d;
}
__device__ __forceinline__ u64 fmul2(u64 a, u64 b) {
    u64 d; asm("mul.rn.f32x2 %0,%1,%2;" : "=l"(d) : "l"(a), "l"(b)); return d;
}
__device__ __forceinline__ u64 fadd2(u64 a, u64 b) {
    u64 d; asm("add.rn.f32x2 %0,%1,%2;" : "=l"(d) : "l"(a), "l"(b)); return d;
}
__device__ __forceinline__ float hsum2(u64 p) { float lo, hi; upk2(p, lo, hi); return lo + hi; }
__device__ __forceinline__ u64 dup2(float v) { return pk2(v, v); }
__device__ __forceinline__ float ex2f(float x) {
    float y; asm("ex2.approx.f32 %0,%1;" : "=f"(y) : "f"(x)); return y;
}

// dot of one 32-float weight row (global or shared, broadcast) vs two packed-16 vectors
__device__ __forceinline__ void dot32x2(const float* __restrict__ w,
                                        const u64  va[16], const u64 vb[16],
                                        float& ra, float& rb) {
    const ulonglong2* wp = reinterpret_cast<const ulonglong2*>(w);
    u64 a0 = 0, a1 = 0, b0 = 0, b1 = 0;
#pragma unroll
    for (int i = 0; i < 8; i++) {
        ulonglong2 wv = wp[i];
        a0 = ffma2(wv.x, va[2 * i], a0);
        a1 = ffma2(wv.y, va[2 * i + 1], a1);
        b0 = ffma2(wv.x, vb[2 * i], b0);
        b1 = ffma2(wv.y, vb[2 * i + 1], b1);
    }
    ra = hsum2(fadd2(a0, a1));
    rb = hsum2(fadd2(b0, b1));
}

// packed layernorm over 16 pairs; g/b read broadcast from global
__device__ __forceinline__ void ln32p(const u64 v[16], const float* __restrict__ g,
                                      const float* __restrict__ b, u64 o[16]) {
    u64 s = 0;
#pragma unroll
    for (int i = 0; i < 16; i++) s = fadd2(s, v[i]);
    float m = hsum2(s) * 0.03125f;
    u64 mneg = dup2(-m);
    u64 q = 0;
#pragma unroll
    for (int i = 0; i < 16; i++) { u64 d = fadd2(v[i], mneg); o[i] = d; q = ffma2(d, d, q); }
    float var = hsum2(q) * 0.03125f;
    u64 iv = dup2(rsqrtf(var + 1e-5f));
    const ulonglong2* gp = reinterpret_cast<const ulonglong2*>(g);
    const ulonglong2* bp = reinterpret_cast<const ulonglong2*>(b);
#pragma unroll
    for (int i = 0; i < 8; i++) {
        ulonglong2 gg = gp[i], bb = bp[i];
        o[2 * i]     = ffma2(fmul2(o[2 * i], iv), gg.x, bb.x);
        o[2 * i + 1] = ffma2(fmul2(o[2 * i + 1], iv), gg.y, bb.y);
    }
}

__device__ __forceinline__ void embed_token(const float* __restrict__ fpw,
                                            const float* __restrict__ fpb,
                                            const float* __restrict__ lemb,
                                            const float* __restrict__ fB,
                                            const float* __restrict__ xp,
                                            int lay, float h[D_MODEL]) {
    const float p0 = __ldg(xp), p1 = __ldg(xp + 1), p2 = __ldg(xp + 2);
    const float4* le = reinterpret_cast<const float4*>(lemb + lay * 32);
#pragma unroll
    for (int i = 0; i < 8; i++) {
        float4 lv = __ldg(le + i);
        h[4 * i]     = __ldg(fpb + 4 * i)     + lv.x;
        h[4 * i + 1] = __ldg(fpb + 4 * i + 1) + lv.y;
        h[4 * i + 2] = __ldg(fpb + 4 * i + 2) + lv.z;
        h[4 * i + 3] = __ldg(fpb + 4 * i + 3) + lv.w;
    }
#pragma unroll 1
    for (int k = 0; k < INDIM; k++) {
        float xk = __ldg(xp + k);
#pragma unroll
        for (int c = 0; c < D_MODEL; c++) h[c] = fmaf(xk, __ldg(fpw + c * INDIM + k), h[c]);
    }
#pragma unroll
    for (int j = 0; j < 16; j++) {
        float pr = 6.28318530717958647692f *
                   (p0 * __ldg(fB + j) + p1 * __ldg(fB + 16 + j) + p2 * __ldg(fB + 32 + j));
        float sn, cs;
        sincosf(pr, &sn, &cs);
        h[j] += sn;
        h[j + 16] += cs;
    }
}

__global__ void __launch_bounds__(128, 3) spai_kernel(
    const float* __restrict__ x, const int* __restrict__ layers,
    const float* __restrict__ fpw, const float* __restrict__ fpb,
    const float* __restrict__ lemb, const float* __restrict__ fB,
    const float* __restrict__ ipw, const float* __restrict__ ipb,
    const float* __restrict__ opw, const float* __restrict__ opb,
    const float* __restrict__ g1, const float* __restrict__ b1,
    const float* __restrict__ w1, const float* __restrict__ bb1,
    const float* __restrict__ w2, const float* __restrict__ bb2,
    const float* __restrict__ g2, const float* __restrict__ b2,
    const float* __restrict__ nog, const float* __restrict__ nob,
    const float* __restrict__ hw, const float* __restrict__ hb,
    float* __restrict__ out)
{
    extern __shared__ float sw[];
    float* ks = sw + OFF_K;
    float* vs = sw + OFF_V;
    const int tid = threadIdx.x;
    const int rowA = 2 * tid, rowB = 2 * tid + 1;
    const long long ga = (long long)blockIdx.x * WIN + rowA;
    const long long gb = ga + 1;

    // ---------------- embedding (weights straight from global/L2) ----------------
    float hsa[D_MODEL], hsb[D_MODEL];
    embed_token(fpw, fpb, lemb, fB, x + (size_t)ga * INDIM, __ldg(layers + ga), hsa);
    embed_token(fpw, fpb, lemb, fB, x + (size_t)gb * INDIM, __ldg(layers + gb), hsb);

    u64 hA[16], hB[16];
#pragma unroll
    for (int i = 0; i < 16; i++) { hA[i] = pk2(hsa[2 * i], hsa[2 * i + 1]); hB[i] = pk2(hsb[2 * i], hsb[2 * i + 1]); }

    // ---------------- transformer layers ----------------
    for (int li = 0; li < NLAYER; li++) {
        const float* Lipw = ipw + li * 3072;
        const float* Lipb = ipb + li * 96;
        const float* Lopw = opw + li * 1024;
        const float* Lopb = opb + li * 32;
        const float* Lg1  = g1 + li * 32;
        const float* Lb1  = b1 + li * 32;
        const float* Lw1  = w1 + li * 2048;
        const float* Lbb1 = bb1 + li * 64;
        const float* Lw2  = w2 + li * 2048;
        const float* Lbb2 = bb2 + li * 32;
        const float* Lg2  = g2 + li * 32;
        const float* Lb2  = b2 + li * 32;

        __syncthreads();   // K/V (and staged w2T) from previous layer fully consumed

        // ----- QKV (weights broadcast from L2) -----
        // 1/sqrt(8) * log2(e) folded into q so softmax uses raw ex2
        const float rs2 = 0.51006464544565f;
        u64 qA[16], qB[16];
#pragma unroll 2
        for (int o = 0; o < 32; o += 2) {
            float a0, b0, a1, b1v;
            dot32x2(Lipw + o * 32, hA, hB, a0, b0);
            dot32x2(Lipw + (o + 1) * 32, hA, hB, a1, b1v);
            float i0 = __ldg(Lipb + o), i1 = __ldg(Lipb + o + 1);
            qA[o >> 1] = pk2((a0 + i0) * rs2, (a1 + i1) * rs2);
            qB[o >> 1] = pk2((b0 + i0) * rs2, (b1v + i1) * rs2);
        }
#pragma unroll 2
        for (int o = 32; o < 96; o += 4) {
            float ta[4], tb[4];
#pragma unroll
            for (int u = 0; u < 4; u++) {
                dot32x2(Lipw + (o + u) * 32, hA, hB, ta[u], tb[u]);
                float bi = __ldg(Lipb + o + u);
                ta[u] += bi; tb[u] += bi;
            }
            float* dst = (o < 64) ? ks : vs;
            int c = (o < 64) ? (o - 32) : (o - 64);
            *reinterpret_cast<float4*>(dst + rowA * KV_STRIDE + c) = make_float4(ta[0], ta[1], ta[2], ta[3]);
            *reinterpret_cast<float4*>(dst + rowB * KV_STRIDE + c) = make_float4(tb[0], tb[1], tb[2], tb[3]);
        }
        __syncthreads();

        // ----- attention (R4 body: simple indexed loads, ptxas schedules) -----
        u64 oaA[16], oaB[16];
#pragma unroll
        for (int i = 0; i < 16; i++) { oaA[i] = 0; oaB[i] = 0; }
        float la[NHEAD] = {0.f, 0.f, 0.f, 0.f};
        float lb[NHEAD] = {0.f, 0.f, 0.f, 0.f};

#pragma unroll 2
        for (int j = 0; j < WIN; j++) {
            const ulonglong2* kp = reinterpret_cast<const ulonglong2*>(ks + j * KV_STRIDE);
            const ulonglong2* vp = reinterpret_cast<const ulonglong2*>(vs + j * KV_STRIDE);
#pragma unroll
            for (int hh = 0; hh < NHEAD; hh++) {
                ulonglong2 kA = kp[2 * hh], kB = kp[2 * hh + 1];
                u64 sa = fmul2(kA.x, qA[4 * hh]);
                sa = ffma2(kA.y, qA[4 * hh + 1], sa);
                sa = ffma2(kB.x, qA[4 * hh + 2], sa);
                sa = ffma2(kB.y, qA[4 * hh + 3], sa);
                u64 sb = fmul2(kA.x, qB[4 * hh]);
                sb = ffma2(kA.y, qB[4 * hh + 1], sb);
                sb = ffma2(kB.x, qB[4 * hh + 2], sb);
                sb = ffma2(kB.y, qB[4 * hh + 3], sb);
                float pa = ex2f(hsum2(sa));
                float pb = ex2f(hsum2(sb));
                la[hh] += pa; lb[hh] += pb;
                u64 ppa = dup2(pa), ppb = dup2(pb);
                ulonglong2 vA = vp[2 * hh], vB = vp[2 * hh + 1];
                oaA[4 * hh]     = ffma2(ppa, vA.x, oaA[4 * hh]);
                oaA[4 * hh + 1] = ffma2(ppa, vA.y, oaA[4 * hh + 1]);
                oaA[4 * hh + 2] = ffma2(ppa, vB.x, oaA[4 * hh + 2]);
                oaA[4 * hh + 3] = ffma2(ppa, vB.y, oaA[4 * hh + 3]);
                oaB[4 * hh]     = ffma2(ppb, vA.x, oaB[4 * hh]);
                oaB[4 * hh + 1] = ffma2(ppb, vA.y, oaB[4 * hh + 1]);
                oaB[4 * hh + 2] = ffma2(ppb, vB.x, oaB[4 * hh + 2]);
                oaB[4 * hh + 3] = ffma2(ppb, vB.y, oaB[4 * hh + 3]);
            }
        }

#pragma unroll
        for (int hh = 0; hh < NHEAD; hh++) {
            u64 rla = dup2(1.0f / la[hh]), rlb = dup2(1.0f / lb[hh]);
#pragma unroll
            for (int p = 0; p < 4; p++) {
                oaA[4 * hh + p] = fmul2(oaA[4 * hh + p], rla);
                oaB[4 * hh + p] = fmul2(oaB[4 * hh + p], rlb);
            }
        }

        // ----- stage w2 transposed into (now dead) K buffer -----
        __syncthreads();                    // everyone done reading ks
        for (int i = tid; i < 2048; i += 128) {
            int c = i >> 6, f = i & 63;
            ks[f * 32 + c] = __ldg(Lw2 + i);
        }
        // no sync needed yet: each thread next does out-proj/LN (no ks access);
        // sync before FF reads ks below.

        // ----- out proj + residual + LN1 -----
        u64 t1a[16], t1b[16];
#pragma unroll 2
        for (int c = 0; c < 32; c += 2) {
            float x0a, x0b, x1a, x1b;
            dot32x2(Lopw + c * 32, oaA, oaB, x0a, x0b);
            dot32x2(Lopw + (c + 1) * 32, oaA, oaB, x1a, x1b);
            float o0 = __ldg(Lopb + c), o1 = __ldg(Lopb + c + 1);
            t1a[c >> 1] = fadd2(hA[c >> 1], pk2(x0a + o0, x1a + o1));
            t1b[c >> 1] = fadd2(hB[c >> 1], pk2(x0b + o0, x1b + o1));
        }
        ln32p(t1a, Lg1, Lb1, hA);
        ln32p(t1b, Lg1, Lb1, hB);
        __syncthreads();                    // w2T staged before FF reads it

        // ----- FF -----
        u64 f2a[16], f2b[16];
        {
            const ulonglong2* bp = reinterpret_cast<const ulonglong2*>(Lbb2);
#pragma unroll
            for (int i = 0; i < 8; i++) {
                ulonglong2 bb = bp[i];
                f2a[2 * i] = bb.x; f2a[2 * i + 1] = bb.y;
                f2b[2 * i] = bb.x; f2b[2 * i + 1] = bb.y;
            }
        }
#pragma unroll 2
        for (int f = 0; f < DFF; f++) {
            float ta, tb;
            dot32x2(Lw1 + f * 32, hA, hB, ta, tb);
            float bi = __ldg(Lbb1 + f);
            ta += bi; tb += bi;
            float gla = 0.5f * ta * (1.0f + erff(ta * 0.70710678118654752440f));
            float glb = 0.5f * tb * (1.0f + erff(tb * 0.70710678118654752440f));
            u64 gga = dup2(gla), ggb = dup2(glb);
            const ulonglong2* wp = reinterpret_cast<const ulonglong2*>(ks + f * 32);
#pragma unroll
            for (int i = 0; i < 8; i++) {
                ulonglong2 w2v = wp[i];
                f2a[2 * i]     = ffma2(gga, w2v.x, f2a[2 * i]);
                f2a[2 * i + 1] = ffma2(gga, w2v.y, f2a[2 * i + 1]);
                f2b[2 * i]     = ffma2(ggb, w2v.x, f2b[2 * i]);
                f2b[2 * i + 1] = ffma2(ggb, w2v.y, f2b[2 * i + 1]);
            }
        }
        u64 t2a[16], t2b[16];
#pragma unroll
        for (int i = 0; i < 16; i++) { t2a[i] = fadd2(hA[i], f2a[i]); t2b[i] = fadd2(hB[i], f2b[i]); }
        ln32p(t2a, Lg2, Lb2, hA);
        ln32p(t2b, Lg2, Lb2, hB);
    }

    // ---------------- final LN + head ----------------
    u64 na[16], nb[16];
    ln32p(hA, nog, nob, na);
    ln32p(hB, nog, nob, nb);

    float* outA = out + (size_t)ga * HOUT;
    float* outB = out + (size_t)gb * HOUT;
#pragma unroll 1
    for (int c = 0; c < HOUT; c++) {
        float ta, tb;
        dot32x2(hw + c * 32, na, nb, ta, tb);
        float bi = __ldg(hb + c);
        outA[c] = ta + bi;
        outB[c] = tb + bi;
    }
}

extern "C" void kernel_launch(void* const* d_in, const int* in_sizes, int n_in,
                              void* d_out, int out_size) {
    const float* x    = (const float*)d_in[0];
    const int*   lays = (const int*)d_in[1];
    const float* fpw  = (const float*)d_in[2];
    const float* fpb  = (const float*)d_in[3];
    const float* lemb = (const float*)d_in[4];
    const float* fB   = (const float*)d_in[5];
    const float* ipw  = (const float*)d_in[6];
    const float* ipb  = (const float*)d_in[7];
    const float* opw  = (const float*)d_in[8];
    const float* opb  = (const float*)d_in[9];
    const float* g1   = (const float*)d_in[10];
    const float* b1   = (const float*)d_in[11];
    const float* w1   = (const float*)d_in[12];
    const float* bb1  = (const float*)d_in[13];
    const float* w2   = (const float*)d_in[14];
    const float* bb2  = (const float*)d_in[15];
    const float* g2   = (const float*)d_in[16];
    const float* b2   = (const float*)d_in[17];
    const float* nog  = (const float*)d_in[18];
    const float* nob  = (const float*)d_in[19];
    const float* hw   = (const float*)d_in[20];
    const float* hb   = (const float*)d_in[21];
    float* out = (float*)d_out;

    const int tokens = in_sizes[0] / INDIM;
    const int grid = tokens / WIN;

    cudaFuncSetAttribute(spai_kernel, cudaFuncAttributeMaxDynamicSharedMemorySize, SMEM_BYTES);
    spai_kernel<<<grid, 128, SMEM_BYTES>>>(x, lays, fpw, fpb, lemb, fB, ipw, ipb, opw, opb,
                                           g1, b1, w1, bb1, w2, bb2, g2, b2, nog, nob, hw, hb,
                                           out);
}

// round 7
// speedup vs baseline: 1.0858x; 1.0858x over previous
#include <cuda_runtime.h>
#include <math.h>

#define D_MODEL 32
#define NHEAD 4
#define WIN 256
#define DFF 64
#define INDIM 58
#define HOUT 25
#define NLAYER 4

// ---- shared memory (floats): K(8192) V(8192) stage(4*528) perm(160) ----
#define OFF_K 0
#define OFF_V 8192
#define OFF_S 16384
#define OFF_P (16384 + 4*528)          // 18496
#define SMEM_FLOATS (OFF_P + 160)      // 18656
#define SMEM_BYTES (SMEM_FLOATS * 4)   // 74624 -> 3 CTAs/SM

typedef unsigned long long u64;

__device__ __forceinline__ u64 pk2(float lo, float hi) {
    u64 r; asm("mov.b64 %0,{%1,%2};" : "=l"(r) : "f"(lo), "f"(hi)); return r;
}
__device__ __forceinline__ void upk2(u64 p, float& lo, float& hi) {
    asm("mov.b64 {%0,%1},%2;" : "=f"(lo), "=f"(hi) : "l"(p));
}
__device__ __forceinline__ u64 ffma2(u64 a, u64 b, u64 c) {
    u64 d; asm("fma.rn.f32x2 %0,%1,%2,%3;" : "=l"(d) : "l"(a), "l"(b), "l"(c)); return d;
}
__device__ __forceinline__ u64 fmul2(u64 a, u64 b) {
    u64 d; asm("mul.rn.f32x2 %0,%1,%2;" : "=l"(d) : "l"(a), "l"(b)); return d;
}
__device__ __forceinline__ u64 fadd2(u64 a, u64 b) {
    u64 d; asm("add.rn.f32x2 %0,%1,%2;" : "=l"(d) : "l"(a), "l"(b)); return d;
}
__device__ __forceinline__ float hsum2(u64 p) { float lo, hi; upk2(p, lo, hi); return lo + hi; }
__device__ __forceinline__ u64 dup2(float v) { return pk2(v, v); }
__device__ __forceinline__ float ex2f(float x) {
    float y; asm("ex2.approx.f32 %0,%1;" : "=f"(y) : "f"(x)); return y;
}

// dot of one 32-float weight row (smem broadcast) vs two packed-16 token vectors
__device__ __forceinline__ void dot32x2(const float* w, const u64 va[16], const u64 vb[16],
                                        float& ra, float& rb) {
    const ulonglong2* wp = reinterpret_cast<const ulonglong2*>(w);
    u64 a0 = 0, a1 = 0, b0 = 0, b1 = 0;
#pragma unroll
    for (int i = 0; i < 8; i++) {
        ulonglong2 wv = wp[i];
        a0 = ffma2(wv.x, va[2 * i], a0);
        a1 = ffma2(wv.y, va[2 * i + 1], a1);
        b0 = ffma2(wv.x, vb[2 * i], b0);
        b1 = ffma2(wv.y, vb[2 * i + 1], b1);
    }
    ra = hsum2(fadd2(a0, a1));
    rb = hsum2(fadd2(b0, b1));
}

// packed layernorm over 16 pairs; g/b from smem
__device__ __forceinline__ void ln32p(const u64 v[16], const float* g, const float* b, u64 o[16]) {
    u64 s = 0;
#pragma unroll
    for (int i = 0; i < 16; i++) s = fadd2(s, v[i]);
    float m = hsum2(s) * 0.03125f;
    u64 mneg = dup2(-m);
    u64 q = 0;
#pragma unroll
    for (int i = 0; i < 16; i++) { u64 d = fadd2(v[i], mneg); o[i] = d; q = ffma2(d, d, q); }
    float var = hsum2(q) * 0.03125f;
    u64 iv = dup2(rsqrtf(var + 1e-5f));
    const ulonglong2* gp = reinterpret_cast<const ulonglong2*>(g);
    const ulonglong2* bp = reinterpret_cast<const ulonglong2*>(b);
#pragma unroll
    for (int i = 0; i < 8; i++) {
        ulonglong2 gg = gp[i], bb = bp[i];
        o[2 * i]     = ffma2(fmul2(o[2 * i], iv), gg.x, bb.x);
        o[2 * i + 1] = ffma2(fmul2(o[2 * i + 1], iv), gg.y, bb.y);
    }
}

// embed from staged fpw/fpb/fB (smem), lemb via __ldg
__device__ __forceinline__ void embed_token(const float* sf, const float* __restrict__ lemb,
                                            const float* __restrict__ xp, int lay,
                                            float h[D_MODEL]) {
    const float p0 = __ldg(xp), p1 = __ldg(xp + 1), p2 = __ldg(xp + 2);
    const float4* le = reinterpret_cast<const float4*>(lemb + lay * 32);
#pragma unroll
    for (int i = 0; i < 8; i++) {
        float4 lv = __ldg(le + i);
        h[4 * i]     = sf[1856 + 4 * i]     + lv.x;
        h[4 * i + 1] = sf[1856 + 4 * i + 1] + lv.y;
        h[4 * i + 2] = sf[1856 + 4 * i + 2] + lv.z;
        h[4 * i + 3] = sf[1856 + 4 * i + 3] + lv.w;
    }
#pragma unroll 1
    for (int k = 0; k < INDIM; k++) {
        float xk = __ldg(xp + k);
#pragma unroll
        for (int c = 0; c < D_MODEL; c++) h[c] = fmaf(xk, sf[c * INDIM + k], h[c]);
    }
#pragma unroll
    for (int j = 0; j < 16; j++) {
        float pr = 6.28318530717958647692f *
                   (p0 * sf[1888 + j] + p1 * sf[1904 + j] + p2 * sf[1920 + j]);
        float sn, cs;
        sincosf(pr, &sn, &cs);
        h[j] += sn;
        h[j + 16] += cs;
    }
}

__global__ void __launch_bounds__(128, 3) spai_kernel(
    const float* __restrict__ x, const int* __restrict__ layers,
    const float* __restrict__ fpw, const float* __restrict__ fpb,
    const float* __restrict__ lemb, const float* __restrict__ fB,
    const float* __restrict__ ipw, const float* __restrict__ ipb,
    const float* __restrict__ opw, const float* __restrict__ opb,
    const float* __restrict__ g1, const float* __restrict__ b1,
    const float* __restrict__ w1, const float* __restrict__ bb1,
    const float* __restrict__ w2, const float* __restrict__ bb2,
    const float* __restrict__ g2, const float* __restrict__ b2,
    const float* __restrict__ nog, const float* __restrict__ nob,
    const float* __restrict__ hw, const float* __restrict__ hb,
    float* __restrict__ out)
{
    extern __shared__ float sw[];
    float* ks   = sw + OFF_K;
    float* vs   = sw + OFF_V;
    float* stg  = sw + OFF_S;
    float* perm = sw + OFF_P;
    const int tid = threadIdx.x;
    const int rowA = 2 * tid, rowB = 2 * tid + 1;
    const long long ga = (long long)blockIdx.x * WIN + rowA;
    const long long gb = ga + 1;

    // ---------------- embedding: stage <- fpw(1856) fpb(32) fB(48) ----------------
    for (int i = tid; i < 1936; i += 128) {
        float v = (i < 1856) ? __ldg(fpw + i)
                : (i < 1888) ? __ldg(fpb + i - 1856)
                             : __ldg(fB + i - 1888);
        stg[i] = v;
    }
    __syncthreads();

    float hsa[D_MODEL], hsb[D_MODEL];
    embed_token(stg, lemb, x + (size_t)ga * INDIM, __ldg(layers + ga), hsa);
    embed_token(stg, lemb, x + (size_t)gb * INDIM, __ldg(layers + gb), hsb);

    u64 hA[16], hB[16];
#pragma unroll
    for (int i = 0; i < 16; i++) { hA[i] = pk2(hsa[2 * i], hsa[2 * i + 1]); hB[i] = pk2(hsb[2 * i], hsb[2 * i + 1]); }

    // ---------------- preload ipw slots 0,1 (layer 0, q rows 0-31) ----------------
    {
        float4 w0v = __ldg(reinterpret_cast<const float4*>(ipw) + tid);
        float4 w1v = __ldg(reinterpret_cast<const float4*>(ipw + 512) + tid);
        float b0v = 0.f, b1v = 0.f;
        if (tid < 16) { b0v = __ldg(ipb + tid); b1v = __ldg(ipb + 16 + tid); }
        __syncthreads();                     // embed done reading stage
        reinterpret_cast<float4*>(stg)[tid] = w0v;
        reinterpret_cast<float4*>(stg + 528)[tid] = w1v;
        if (tid < 16) { stg[512 + tid] = b0v; stg[528 + 512 + tid] = b1v; }
        __syncthreads();
    }

    u64 hstash[32];
    volatile u64* hs = hstash;

    // ---------------- transformer layers ----------------
#pragma unroll 1
    for (int li = 0; li < NLAYER; li++) {
        const float* Lipw = ipw + li * 3072;
        const float* Lipb = ipb + li * 96;
        const float* Lopw = opw + li * 1024;
        const float* Lopb = opb + li * 32;
        const float* Lw1  = w1 + li * 2048;
        const float* Lbb1 = bb1 + li * 64;
        const float* Lw2  = w2 + li * 2048;

        const float rs2 = 0.51006464544565f;   // (1/sqrt(8))*log2(e) folded into q
        u64 qA[16], qB[16];

        // ===== Step Q: use slots 0,1 (ipw rows 0-31); prefetch slots 2,3 <- rows 32-63
        {
            float4 pw0 = __ldg(reinterpret_cast<const float4*>(Lipw + 1024) + tid);
            float4 pw1 = __ldg(reinterpret_cast<const float4*>(Lipw + 1536) + tid);
            float pb0 = 0.f, pb1 = 0.f;
            if (tid < 16) { pb0 = __ldg(Lipb + 32 + tid); pb1 = __ldg(Lipb + 48 + tid); }

#pragma unroll 2
            for (int o = 0; o < 32; o += 2) {
                const float* wr0 = stg + (o >> 4) * 528 + (o & 15) * 32;
                const float* wr1 = stg + ((o + 1) >> 4) * 528 + ((o + 1) & 15) * 32;
                float a0, b0v, a1, b1v;
                dot32x2(wr0, hA, hB, a0, b0v);
                dot32x2(wr1, hA, hB, a1, b1v);
                float i0 = stg[(o >> 4) * 528 + 512 + (o & 15)];
                float i1 = stg[((o + 1) >> 4) * 528 + 512 + ((o + 1) & 15)];
                qA[o >> 1] = pk2((a0 + i0) * rs2, (a1 + i1) * rs2);
                qB[o >> 1] = pk2((b0v + i0) * rs2, (b1v + i1) * rs2);
            }
            reinterpret_cast<float4*>(stg + 2 * 528)[tid] = pw0;
            reinterpret_cast<float4*>(stg + 3 * 528)[tid] = pw1;
            if (tid < 16) { stg[2 * 528 + 512 + tid] = pb0; stg[3 * 528 + 512 + tid] = pb1; }
            __syncthreads();
        }

        // ===== Step K: use slots 2,3 (rows 32-63); prefetch 0,1 <- rows 64-95 (V)
        {
            float4 pw0 = __ldg(reinterpret_cast<const float4*>(Lipw + 2048) + tid);
            float4 pw1 = __ldg(reinterpret_cast<const float4*>(Lipw + 2560) + tid);
            float pb0 = 0.f, pb1 = 0.f;
            if (tid < 16) { pb0 = __ldg(Lipb + 64 + tid); pb1 = __ldg(Lipb + 80 + tid); }

            const float* base = stg + 2 * 528;
            const int rot = tid & 7;
#pragma unroll
            for (int gg = 0; gg < 8; gg++) {
                int g = (gg + rot) & 7;
                const float* wb = base + (g >> 2) * 528 + (g & 3) * 128;
                const float* bb = base + (g >> 2) * 528 + 512 + (g & 3) * 4;
                float ta[4], tb[4];
#pragma unroll
                for (int u = 0; u < 4; u++) {
                    dot32x2(wb + u * 32, hA, hB, ta[u], tb[u]);
                    float bi = bb[u];
                    ta[u] += bi; tb[u] += bi;
                }
                *reinterpret_cast<float4*>(ks + rowA * 32 + 4 * g) = make_float4(ta[0], ta[1], ta[2], ta[3]);
                *reinterpret_cast<float4*>(ks + rowB * 32 + 4 * g) = make_float4(tb[0], tb[1], tb[2], tb[3]);
            }
            reinterpret_cast<float4*>(stg)[tid] = pw0;
            reinterpret_cast<float4*>(stg + 528)[tid] = pw1;
            if (tid < 16) { stg[512 + tid] = pb0; stg[528 + 512 + tid] = pb1; }
            __syncthreads();
        }

        // ===== Step V: use slots 0,1 (rows 64-95); prefetch 2,3 <- opw(+opb); + perm(LN,bb2)
        {
            float4 pw0 = __ldg(reinterpret_cast<const float4*>(Lopw) + tid);
            float4 pw1 = __ldg(reinterpret_cast<const float4*>(Lopw + 512) + tid);
            float pb0 = 0.f, pb1 = 0.f;
            if (tid < 16) { pb0 = __ldg(Lopb + tid); pb1 = __ldg(Lopb + 16 + tid); }
            const float* lnp = (tid < 32) ? (g1 + li * 32) : (tid < 64) ? (b1 + li * 32)
                              : (tid < 96) ? (g2 + li * 32) : (b2 + li * 32);
            float lnv = __ldg(lnp + (tid & 31));
            float bbv = 0.f;
            if (tid < 32) bbv = __ldg(bb2 + li * 32 + tid);

            const float* base = stg;
            const int rot = tid & 7;
#pragma unroll
            for (int gg = 0; gg < 8; gg++) {
                int g = (gg + rot) & 7;
                const float* wb = base + (g >> 2) * 528 + (g & 3) * 128;
                const float* bb = base + (g >> 2) * 528 + 512 + (g & 3) * 4;
                float ta[4], tb[4];
#pragma unroll
                for (int u = 0; u < 4; u++) {
                    dot32x2(wb + u * 32, hA, hB, ta[u], tb[u]);
                    float bi = bb[u];
                    ta[u] += bi; tb[u] += bi;
                }
                *reinterpret_cast<float4*>(vs + rowA * 32 + 4 * g) = make_float4(ta[0], ta[1], ta[2], ta[3]);
                *reinterpret_cast<float4*>(vs + rowB * 32 + 4 * g) = make_float4(tb[0], tb[1], tb[2], tb[3]);
            }
            reinterpret_cast<float4*>(stg + 2 * 528)[tid] = pw0;
            reinterpret_cast<float4*>(stg + 3 * 528)[tid] = pw1;
            if (tid < 16) { stg[2 * 528 + 512 + tid] = pb0; stg[3 * 528 + 512 + tid] = pb1; }
            perm[tid] = lnv;
            if (tid < 32) perm[128 + tid] = bbv;
            __syncthreads();
        }

        // stash h (cold during attention) to local
#pragma unroll
        for (int i = 0; i < 16; i++) { hs[i] = hA[i]; hs[16 + i] = hB[i]; }

        // ===== attention =====
        u64 oaA[16], oaB[16];
#pragma unroll
        for (int i = 0; i < 16; i++) { oaA[i] = 0; oaB[i] = 0; }
        float la[NHEAD] = {0.f, 0.f, 0.f, 0.f};
        float lb[NHEAD] = {0.f, 0.f, 0.f, 0.f};

#pragma unroll 2
        for (int j = 0; j < WIN; j++) {
            const ulonglong2* kp = reinterpret_cast<const ulonglong2*>(ks + j * 32);
            const ulonglong2* vp = reinterpret_cast<const ulonglong2*>(vs + j * 32);
#pragma unroll
            for (int hh = 0; hh < NHEAD; hh++) {
                ulonglong2 kA = kp[2 * hh], kB = kp[2 * hh + 1];
                u64 sa = fmul2(kA.x, qA[4 * hh]);
                sa = ffma2(kA.y, qA[4 * hh + 1], sa);
                sa = ffma2(kB.x, qA[4 * hh + 2], sa);
                sa = ffma2(kB.y, qA[4 * hh + 3], sa);
                u64 sb = fmul2(kA.x, qB[4 * hh]);
                sb = ffma2(kA.y, qB[4 * hh + 1], sb);
                sb = ffma2(kB.x, qB[4 * hh + 2], sb);
                sb = ffma2(kB.y, qB[4 * hh + 3], sb);
                float pa = ex2f(hsum2(sa));
                float pb = ex2f(hsum2(sb));
                la[hh] += pa; lb[hh] += pb;
                u64 ppa = dup2(pa), ppb = dup2(pb);
                ulonglong2 vA = vp[2 * hh], vB = vp[2 * hh + 1];
                oaA[4 * hh]     = ffma2(ppa, vA.x, oaA[4 * hh]);
                oaA[4 * hh + 1] = ffma2(ppa, vA.y, oaA[4 * hh + 1]);
                oaA[4 * hh + 2] = ffma2(ppa, vB.x, oaA[4 * hh + 2]);
                oaA[4 * hh + 3] = ffma2(ppa, vB.y, oaA[4 * hh + 3]);
                oaB[4 * hh]     = ffma2(ppb, vA.x, oaB[4 * hh]);
                oaB[4 * hh + 1] = ffma2(ppb, vA.y, oaB[4 * hh + 1]);
                oaB[4 * hh + 2] = ffma2(ppb, vB.x, oaB[4 * hh + 2]);
                oaB[4 * hh + 3] = ffma2(ppb, vB.y, oaB[4 * hh + 3]);
            }
        }

#pragma unroll
        for (int hh = 0; hh < NHEAD; hh++) {
            u64 rla = dup2(1.0f / la[hh]), rlb = dup2(1.0f / lb[hh]);
#pragma unroll
            for (int p = 0; p < 4; p++) {
                oaA[4 * hh + p] = fmul2(oaA[4 * hh + p], rla);
                oaB[4 * hh + p] = fmul2(oaB[4 * hh + p], rlb);
            }
        }

        // restore h
#pragma unroll
        for (int i = 0; i < 16; i++) { hA[i] = hs[i]; hB[i] = hs[16 + i]; }

        // ===== Step O: use slots 2,3 (opw); prefetch 0 <- w1 rows0-15+bb1, 1 <- w2T f[0,16)
        {
            float4 pw0 = __ldg(reinterpret_cast<const float4*>(Lw1) + tid);
            float pb0 = 0.f;
            if (tid < 16) pb0 = __ldg(Lbb1 + tid);
            const int tc = tid >> 2, tf = (4 * tid) & 15;
            float4 pt0 = __ldg(reinterpret_cast<const float4*>(Lw2 + tc * 64 + tf));

            const float* base = stg + 2 * 528;
            u64 t1a[16], t1b[16];
#pragma unroll 2
            for (int c = 0; c < 32; c += 2) {
                const float* wr0 = base + (c >> 4) * 528 + (c & 15) * 32;
                const float* wr1 = base + ((c + 1) >> 4) * 528 + ((c + 1) & 15) * 32;
                float x0a, x0b, x1a, x1b;
                dot32x2(wr0, oaA, oaB, x0a, x0b);
                dot32x2(wr1, oaA, oaB, x1a, x1b);
                float o0 = base[(c >> 4) * 528 + 512 + (c & 15)];
                float o1 = base[((c + 1) >> 4) * 528 + 512 + ((c + 1) & 15)];
                t1a[c >> 1] = fadd2(hA[c >> 1], pk2(x0a + o0, x1a + o1));
                t1b[c >> 1] = fadd2(hB[c >> 1], pk2(x0b + o0, x1b + o1));
            }
            ln32p(t1a, perm, perm + 32, hA);
            ln32p(t1b, perm, perm + 32, hB);

            reinterpret_cast<float4*>(stg)[tid] = pw0;
            if (tid < 16) stg[512 + tid] = pb0;
            stg[528 + (tf + 0) * 32 + tc] = pt0.x;
            stg[528 + (tf + 1) * 32 + tc] = pt0.y;
            stg[528 + (tf + 2) * 32 + tc] = pt0.z;
            stg[528 + (tf + 3) * 32 + tc] = pt0.w;
            __syncthreads();
        }

        // ===== FF: 4 steps of 16 f; pairs (0,1),(2,3) alternating
        u64 f2a[16], f2b[16];
        {
            const ulonglong2* bp = reinterpret_cast<const ulonglong2*>(perm + 128);
#pragma unroll
            for (int i = 0; i < 8; i++) {
                ulonglong2 bbv = bp[i];
                f2a[2 * i] = bbv.x; f2a[2 * i + 1] = bbv.y;
                f2b[2 * i] = bbv.x; f2b[2 * i + 1] = bbv.y;
            }
        }
#pragma unroll
        for (int k = 0; k < 4; k++) {
            const int su = (k & 1) ? 2 : 0;
            const int sp = (k & 1) ? 0 : 2;
            const float* w1b = stg + su * 528;
            const float* w2b = stg + (su + 1) * 528;

            // prefetch next
            float4 pw0, pt0, ph0, ph1;
            float pb0 = 0.f, phb = 0.f, pnog = 0.f, pnob = 0.f;
            const int tc = tid >> 2, tf = (4 * tid) & 15;
            bool head = false;
            if (k < 3) {
                pw0 = __ldg(reinterpret_cast<const float4*>(Lw1 + (k + 1) * 512) + tid);
                if (tid < 16) pb0 = __ldg(Lbb1 + (k + 1) * 16 + tid);
                pt0 = __ldg(reinterpret_cast<const float4*>(Lw2 + tc * 64 + (k + 1) * 16 + tf));
            } else if (li < NLAYER - 1) {
                pw0 = __ldg(reinterpret_cast<const float4*>(ipw + (li + 1) * 3072) + tid);
                pt0 = __ldg(reinterpret_cast<const float4*>(ipw + (li + 1) * 3072 + 512) + tid);
                if (tid < 16) { pb0 = __ldg(ipb + (li + 1) * 96 + tid); phb = __ldg(ipb + (li + 1) * 96 + 16 + tid); }
            } else {
                head = true;
                if (tid < 100) {
                    ph0 = __ldg(reinterpret_cast<const float4*>(hw) + 2 * tid);
                    ph1 = __ldg(reinterpret_cast<const float4*>(hw) + 2 * tid + 1);
                }
                if (tid < 25) phb = __ldg(hb + tid);
                if (tid < 32) { pnog = __ldg(nog + tid); pnob = __ldg(nob + tid); }
            }

            // compute 16 f
#pragma unroll 2
            for (int fo = 0; fo < 16; fo++) {
                float ta, tb;
                dot32x2(w1b + fo * 32, hA, hB, ta, tb);
                float bi = w1b[512 + fo];
                ta += bi; tb += bi;
                float gla = 0.5f * ta * (1.0f + erff(ta * 0.70710678118654752440f));
                float glb = 0.5f * tb * (1.0f + erff(tb * 0.70710678118654752440f));
                u64 gga = dup2(gla), ggb = dup2(glb);
                const ulonglong2* wp = reinterpret_cast<const ulonglong2*>(w2b + fo * 32);
#pragma unroll
                for (int i = 0; i < 8; i++) {
                    ulonglong2 w2v = wp[i];
                    f2a[2 * i]     = ffma2(gga, w2v.x, f2a[2 * i]);
                    f2a[2 * i + 1] = ffma2(gga, w2v.y, f2a[2 * i + 1]);
                    f2b[2 * i]     = ffma2(ggb, w2v.x, f2b[2 * i]);
                    f2b[2 * i + 1] = ffma2(ggb, w2v.y, f2b[2 * i + 1]);
                }
            }

            // commit prefetched
            if (k < 3) {
                reinterpret_cast<float4*>(stg + sp * 528)[tid] = pw0;
                if (tid < 16) stg[sp * 528 + 512 + tid] = pb0;
                stg[(sp + 1) * 528 + (tf + 0) * 32 + tc] = pt0.x;
                stg[(sp + 1) * 528 + (tf + 1) * 32 + tc] = pt0.y;
                stg[(sp + 1) * 528 + (tf + 2) * 32 + tc] = pt0.z;
                stg[(sp + 1) * 528 + (tf + 3) * 32 + tc] = pt0.w;
            } else if (!head) {
                reinterpret_cast<float4*>(stg)[tid] = pw0;
                reinterpret_cast<float4*>(stg + 528)[tid] = pt0;
                if (tid < 16) { stg[512 + tid] = pb0; stg[528 + 512 + tid] = phb; }
            } else {
                if (tid < 100) {
                    reinterpret_cast<float4*>(stg)[2 * tid] = ph0;
                    reinterpret_cast<float4*>(stg)[2 * tid + 1] = ph1;
                }
                if (tid < 25) stg[800 + tid] = phb;
                if (tid < 32) { perm[tid] = pnog; perm[32 + tid] = pnob; }
            }
            __syncthreads();
        }

        u64 t2a[16], t2b[16];
#pragma unroll
        for (int i = 0; i < 16; i++) { t2a[i] = fadd2(hA[i], f2a[i]); t2b[i] = fadd2(hB[i], f2b[i]); }
        ln32p(t2a, perm + 64, perm + 96, hA);
        ln32p(t2b, perm + 64, perm + 96, hB);
    }

    // ---------------- final LN + head (stage: hw flat [0,800), hb [800,825); perm: nog,nob)
    u64 na[16], nb[16];
    ln32p(hA, perm, perm + 32, na);
    ln32p(hB, perm, perm + 32, nb);

    float* outA = out + (size_t)ga * HOUT;
    float* outB = out + (size_t)gb * HOUT;
#pragma unroll 1
    for (int c = 0; c < HOUT; c++) {
        float ta, tb;
        dot32x2(stg + c * 32, na, nb, ta, tb);
        float bi = stg[800 + c];
        outA[c] = ta + bi;
        outB[c] = tb + bi;
    }
}

extern "C" void kernel_launch(void* const* d_in, const int* in_sizes, int n_in,
                              void* d_out, int out_size) {
    const float* x    = (const float*)d_in[0];
    const int*   lays = (const int*)d_in[1];
    const float* fpw  = (const float*)d_in[2];
    const float* fpb  = (const float*)d_in[3];
    const float* lemb = (const float*)d_in[4];
    const float* fB   = (const float*)d_in[5];
    const float* ipw  = (const float*)d_in[6];
    const float* ipb  = (const float*)d_in[7];
    const float* opw  = (const float*)d_in[8];
    const float* opb  = (const float*)d_in[9];
    const float* g1   = (const float*)d_in[10];
    const float* b1   = (const float*)d_in[11];
    const float* w1   = (const float*)d_in[12];
    const float* bb1  = (const float*)d_in[13];
    const float* w2   = (const float*)d_in[14];
    const float* bb2  = (const float*)d_in[15];
    const float* g2   = (const float*)d_in[16];
    const float* b2   = (const float*)d_in[17];
    const float* nog  = (const float*)d_in[18];
    const float* nob  = (const float*)d_in[19];
    const float* hw   = (const float*)d_in[20];
    const float* hb   = (const float*)d_in[21];
    float* out = (float*)d_out;

    const int tokens = in_sizes[0] / INDIM;
    const int grid = tokens / WIN;

    cudaFuncSetAttribute(spai_kernel, cudaFuncAttributeMaxDynamicSharedMemorySize, SMEM_BYTES);
    spai_kernel<<<grid, 128, SMEM_BYTES>>>(x, lays, fpw, fpb, lemb, fB, ipw, ipb, opw, opb,
                                           g1, b1, w1, bb1, w2, bb2, g2, b2, nog, nob, hw, hb,
                                           out);
}

// round 9
// speedup vs baseline: 1.4023x; 1.2915x over previous
#include <cuda_runtime.h>
#include <math.h>

#define D_MODEL 32
#define NHEAD 4
#define WIN 256
#define DFF 64
#define INDIM 58
#define HOUT 25
#define NLAYER 4

// ---- shared memory layout (floats) — R1's proven layout ----
#define L_IPW  0      // 96*32
#define L_IPB  3072   // 96
#define L_OPW  3168   // 32*32
#define L_OPB  4192   // 32
#define L_G1   4224
#define L_B1   4256
#define L_W1   4288   // 64*32
#define L_BB1  6336   // 64
#define L_W2T  6400   // 64*32 (transposed lin2_w)
#define L_BB2  8448
#define L_G2   8480
#define L_B2   8512

// embedding overlay
#define E_FPW  0      // 32*58
#define E_FPB  1856
#define E_LEMB 1888   // 12*32
#define E_FB   2272   // 3*16

// head overlay
#define H_NOG  0
#define H_NOB  32
#define H_HW   64     // 25*32
#define H_HB   864

#define KV_STRIDE 36
#define OFF_K  8544
#define OFF_V  (OFF_K + WIN*KV_STRIDE)
#define SMEM_FLOATS (OFF_V + WIN*KV_STRIDE)   // 26976
#define SMEM_BYTES (SMEM_FLOATS * 4)          // 107904 -> 2 CTAs/SM, 16 warps

typedef unsigned long long u64;

__device__ __forceinline__ u64 pk2(float lo, float hi) {
    u64 r; asm("mov.b64 %0,{%1,%2};" : "=l"(r) : "f"(lo), "f"(hi)); return r;
}
__device__ __forceinline__ void upk2(u64 p, float& lo, float& hi) {
    asm("mov.b64 {%0,%1},%2;" : "=f"(lo), "=f"(hi) : "l"(p));
}
__device__ __forceinline__ u64 ffma2(u64 a, u64 b, u64 c) {
    u64 d; asm("fma.rn.f32x2 %0,%1,%2,%3;" : "=l"(d) : "l"(a), "l"(b), "l"(c)); return d;
}
__device__ __forceinline__ u64 fmul2(u64 a, u64 b) {
    u64 d; asm("mul.rn.f32x2 %0,%1,%2;" : "=l"(d) : "l"(a), "l"(b)); return d;
}
__device__ __forceinline__ u64 fadd2(u64 a, u64 b) {
    u64 d; asm("add.rn.f32x2 %0,%1,%2;" : "=l"(d) : "l"(a), "l"(b)); return d;
}
__device__ __forceinline__ float hsum2(u64 p) { float lo, hi; upk2(p, lo, hi); return lo + hi; }
__device__ __forceinline__ u64 dup2(float v) { return pk2(v, v); }
__device__ __forceinline__ float ex2f(float x) {
    float y; asm("ex2.approx.f32 %0,%1;" : "=f"(y) : "f"(x)); return y;
}

// dot of one 32-float weight row (smem broadcast) vs one packed-16 vector
__device__ __forceinline__ float dot32p(const float* w, const u64 v[16]) {
    const ulonglong2* wp = reinterpret_cast<const ulonglong2*>(w);
    u64 a0 = 0, a1 = 0;
#pragma unroll
    for (int i = 0; i < 8; i++) {
        ulonglong2 wv = wp[i];
        a0 = ffma2(wv.x, v[2 * i], a0);
        a1 = ffma2(wv.y, v[2 * i + 1], a1);
    }
    return hsum2(fadd2(a0, a1));
}

// packed layernorm over 16 pairs; g/b from smem
__device__ __forceinline__ void ln32p(const u64 v[16], const float* g, const float* b, u64 o[16]) {
    u64 s = 0;
#pragma unroll
    for (int i = 0; i < 16; i++) s = fadd2(s, v[i]);
    float m = hsum2(s) * 0.03125f;
    u64 mneg = dup2(-m);
    u64 q = 0;
#pragma unroll
    for (int i = 0; i < 16; i++) { u64 d = fadd2(v[i], mneg); o[i] = d; q = ffma2(d, d, q); }
    float var = hsum2(q) * 0.03125f;
    u64 iv = dup2(rsqrtf(var + 1e-5f));
    const ulonglong2* gp = reinterpret_cast<const ulonglong2*>(g);
    const ulonglong2* bp = reinterpret_cast<const ulonglong2*>(b);
#pragma unroll
    for (int i = 0; i < 8; i++) {
        ulonglong2 gg = gp[i], bb = bp[i];
        o[2 * i]     = ffma2(fmul2(o[2 * i], iv), gg.x, bb.x);
        o[2 * i + 1] = ffma2(fmul2(o[2 * i + 1], iv), gg.y, bb.y);
    }
}

__global__ void __launch_bounds__(256, 2) spai_kernel(
    const float* __restrict__ x, const int* __restrict__ layers,
    const float* __restrict__ fpw, const float* __restrict__ fpb,
    const float* __restrict__ lemb, const float* __restrict__ fB,
    const float* __restrict__ ipw, const float* __restrict__ ipb,
    const float* __restrict__ opw, const float* __restrict__ opb,
    const float* __restrict__ g1, const float* __restrict__ b1,
    const float* __restrict__ w1, const float* __restrict__ bb1,
    const float* __restrict__ w2, const float* __restrict__ bb2,
    const float* __restrict__ g2, const float* __restrict__ b2,
    const float* __restrict__ nog, const float* __restrict__ nob,
    const float* __restrict__ hw, const float* __restrict__ hb,
    float* __restrict__ out)
{
    extern __shared__ float sw[];
    float* ks = sw + OFF_K;
    float* vs = sw + OFF_V;
    const int tid = threadIdx.x;
    const long long g = (long long)blockIdx.x * WIN + tid;

    // ---------------- embedding weights ----------------
    for (int i = tid; i < 32 * INDIM; i += 256) sw[E_FPW + i] = fpw[i];
    if (tid < 32) sw[E_FPB + tid] = fpb[tid];
    for (int i = tid; i < 12 * 32; i += 256) sw[E_LEMB + i] = lemb[i];
    if (tid < 48) sw[E_FB + tid] = fB[tid];
    __syncthreads();

    // ---------------- embedding ----------------
    const float* xp = x + (size_t)g * INDIM;
    const float p0 = __ldg(xp), p1 = __ldg(xp + 1), p2 = __ldg(xp + 2);
    const int lay = __ldg(layers + g);

    float hs[D_MODEL];
#pragma unroll
    for (int c = 0; c < D_MODEL; c++) hs[c] = sw[E_FPB + c] + sw[E_LEMB + lay * 32 + c];
#pragma unroll 1
    for (int k = 0; k < INDIM; k++) {
        float xk = __ldg(xp + k);
#pragma unroll
        for (int c = 0; c < D_MODEL; c++) hs[c] = fmaf(xk, sw[E_FPW + c * INDIM + k], hs[c]);
    }
#pragma unroll
    for (int j = 0; j < 16; j++) {
        float pr = 6.28318530717958647692f *
                   (p0 * sw[E_FB + j] + p1 * sw[E_FB + 16 + j] + p2 * sw[E_FB + 32 + j]);
        float sn, cs;
        sincosf(pr, &sn, &cs);
        hs[j] += sn;
        hs[j + 16] += cs;
    }

    u64 h[16];
#pragma unroll
    for (int i = 0; i < 16; i++) h[i] = pk2(hs[2 * i], hs[2 * i + 1]);

    // ---------------- transformer layers ----------------
#pragma unroll 1
    for (int li = 0; li < NLAYER; li++) {
        __syncthreads();
        for (int i = tid; i < 3072; i += 256) sw[L_IPW + i] = ipw[li * 3072 + i];
        if (tid < 96)  sw[L_IPB + tid] = ipb[li * 96 + tid];
        for (int i = tid; i < 1024; i += 256) sw[L_OPW + i] = opw[li * 1024 + i];
        if (tid < 32) {
            sw[L_OPB + tid] = opb[li * 32 + tid];
            sw[L_G1 + tid]  = g1[li * 32 + tid];
            sw[L_B1 + tid]  = b1[li * 32 + tid];
            sw[L_BB2 + tid] = bb2[li * 32 + tid];
            sw[L_G2 + tid]  = g2[li * 32 + tid];
            sw[L_B2 + tid]  = b2[li * 32 + tid];
        }
        for (int i = tid; i < 2048; i += 256) sw[L_W1 + i] = w1[li * 2048 + i];
        if (tid < 64)  sw[L_BB1 + tid] = bb1[li * 64 + tid];
        for (int i = tid; i < 2048; i += 256) {
            int c = i >> 6, f = i & 63;
            sw[L_W2T + f * 32 + c] = w2[li * 2048 + i];
        }
        __syncthreads();

        // ----- QKV -----
        // (1/sqrt(8)) * log2(e) folded into q so softmax uses raw ex2
        const float rs2 = 0.51006464544565f;
        u64 q[16];
#pragma unroll 2
        for (int o = 0; o < 32; o += 2) {
            float a0 = dot32p(sw + L_IPW + o * 32, h) + sw[L_IPB + o];
            float a1 = dot32p(sw + L_IPW + (o + 1) * 32, h) + sw[L_IPB + o + 1];
            q[o >> 1] = pk2(a0 * rs2, a1 * rs2);
        }
#pragma unroll 2
        for (int o = 32; o < 96; o += 4) {
            float t[4];
#pragma unroll
            for (int u = 0; u < 4; u++)
                t[u] = dot32p(sw + L_IPW + (o + u) * 32, h) + sw[L_IPB + o + u];
            float* dst = (o < 64) ? ks : vs;
            int c = (o < 64) ? (o - 32) : (o - 64);
            *reinterpret_cast<float4*>(dst + tid * KV_STRIDE + c) = make_float4(t[0], t[1], t[2], t[3]);
        }
        __syncthreads();

        // ----- attention -----
        u64 oa[16];
#pragma unroll
        for (int i = 0; i < 16; i++) oa[i] = 0;
        float l[NHEAD] = {0.f, 0.f, 0.f, 0.f};

#pragma unroll 2
        for (int j = 0; j < WIN; j++) {
            const ulonglong2* kp = reinterpret_cast<const ulonglong2*>(ks + j * KV_STRIDE);
            const ulonglong2* vp = reinterpret_cast<const ulonglong2*>(vs + j * KV_STRIDE);
#pragma unroll
            for (int hh = 0; hh < NHEAD; hh++) {
                ulonglong2 kA = kp[2 * hh], kB = kp[2 * hh + 1];
                u64 s = fmul2(kA.x, q[4 * hh]);
                s = ffma2(kA.y, q[4 * hh + 1], s);
                s = ffma2(kB.x, q[4 * hh + 2], s);
                s = ffma2(kB.y, q[4 * hh + 3], s);
                float p = ex2f(hsum2(s));
                l[hh] += p;
                u64 pp = dup2(p);
                ulonglong2 vA = vp[2 * hh], vB = vp[2 * hh + 1];
                oa[4 * hh]     = ffma2(pp, vA.x, oa[4 * hh]);
                oa[4 * hh + 1] = ffma2(pp, vA.y, oa[4 * hh + 1]);
                oa[4 * hh + 2] = ffma2(pp, vB.x, oa[4 * hh + 2]);
                oa[4 * hh + 3] = ffma2(pp, vB.y, oa[4 * hh + 3]);
            }
        }

#pragma unroll
        for (int hh = 0; hh < NHEAD; hh++) {
            u64 rl = dup2(1.0f / l[hh]);
#pragma unroll
            for (int p = 0; p < 4; p++) oa[4 * hh + p] = fmul2(oa[4 * hh + p], rl);
        }

        // ----- out proj + residual + LN1 -----
        u64 t1[16];
#pragma unroll 2
        for (int c = 0; c < 32; c += 2) {
            float x0 = dot32p(sw + L_OPW + c * 32, oa) + sw[L_OPB + c];
            float x1 = dot32p(sw + L_OPW + (c + 1) * 32, oa) + sw[L_OPB + c + 1];
            t1[c >> 1] = fadd2(h[c >> 1], pk2(x0, x1));
        }
        ln32p(t1, sw + L_G1, sw + L_B1, h);

        // ----- FF -----
        u64 f2[16];
        {
            const ulonglong2* bp = reinterpret_cast<const ulonglong2*>(sw + L_BB2);
#pragma unroll
            for (int i = 0; i < 8; i++) {
                ulonglong2 bb = bp[i];
                f2[2 * i] = bb.x; f2[2 * i + 1] = bb.y;
            }
        }
#pragma unroll 2
        for (int f = 0; f < DFF; f++) {
            float t = dot32p(sw + L_W1 + f * 32, h) + sw[L_BB1 + f];
            float gl = 0.5f * t * (1.0f + erff(t * 0.70710678118654752440f));
            u64 gg = dup2(gl);
            const ulonglong2* wp = reinterpret_cast<const ulonglong2*>(sw + L_W2T + f * 32);
#pragma unroll
            for (int i = 0; i < 8; i++) {
                ulonglong2 w2v = wp[i];
                f2[2 * i]     = ffma2(gg, w2v.x, f2[2 * i]);
                f2[2 * i + 1] = ffma2(gg, w2v.y, f2[2 * i + 1]);
            }
        }
        u64 t2[16];
#pragma unroll
        for (int i = 0; i < 16; i++) t2[i] = fadd2(h[i], f2[i]);
        ln32p(t2, sw + L_G2, sw + L_B2, h);
    }

    // ---------------- final LN + head ----------------
    __syncthreads();
    if (tid < 32) { sw[H_NOG + tid] = nog[tid]; sw[H_NOB + tid] = nob[tid]; }
    for (int i = tid; i < HOUT * 32; i += 256) sw[H_HW + i] = hw[i];
    if (tid < HOUT) sw[H_HB + tid] = hb[tid];
    __syncthreads();

    u64 hn[16];
    ln32p(h, sw + H_NOG, sw + H_NOB, hn);

    float* op = out + (size_t)g * HOUT;
#pragma unroll 1
    for (int c = 0; c < HOUT; c++)
        op[c] = dot32p(sw + H_HW + c * 32, hn) + sw[H_HB + c];
}

extern "C" void kernel_launch(void* const* d_in, const int* in_sizes, int n_in,
                              void* d_out, int out_size) {
    const float* x    = (const float*)d_in[0];
    const int*   lays = (const int*)d_in[1];
    const float* fpw  = (const float*)d_in[2];
    const float* fpb  = (const float*)d_in[3];
    const float* lemb = (const float*)d_in[4];
    const float* fB   = (const float*)d_in[5];
    const float* ipw  = (const float*)d_in[6];
    const float* ipb  = (const float*)d_in[7];
    const float* opw  = (const float*)d_in[8];
    const float* opb  = (const float*)d_in[9];
    const float* g1   = (const float*)d_in[10];
    const float* b1   = (const float*)d_in[11];
    const float* w1   = (const float*)d_in[12];
    const float* bb1  = (const float*)d_in[13];
    const float* w2   = (const float*)d_in[14];
    const float* bb2  = (const float*)d_in[15];
    const float* g2   = (const float*)d_in[16];
    const float* b2   = (const float*)d_in[17];
    const float* nog  = (const float*)d_in[18];
    const float* nob  = (const float*)d_in[19];
    const float* hw   = (const float*)d_in[20];
    const float* hb   = (const float*)d_in[21];
    float* out = (float*)d_out;

    const int tokens = in_sizes[0] / INDIM;
    const int grid = tokens / WIN;

    cudaFuncSetAttribute(spai_kernel, cudaFuncAttributeMaxDynamicSharedMemorySize, SMEM_BYTES);
    spai_kernel<<<grid, 256, SMEM_BYTES>>>(x, lays, fpw, fpb, lemb, fB, ipw, ipb, opw, opb,
                                           g1, b1, w1, bb1, w2, bb2, g2, b2, nog, nob, hw, hb,
                                           out);
}

// round 12
// speedup vs baseline: 1.6164x; 1.1526x over previous
#include <cuda_runtime.h>
#include <math.h>

#define D_MODEL 32
#define NHEAD 4
#define WIN 256
#define DFF 64
#define INDIM 58
#define HOUT 25
#define NLAYER 4

// ---- shared memory layout (floats) ----
#define L_IPW  0      // 96*32
#define L_IPB  3072   // 96
#define L_OPW  3168   // 32*32
#define L_OPB  4192   // 32
#define L_G1   4224
#define L_B1   4256
#define L_W1   4288   // 64*32
#define L_BB1  6336   // 64
#define L_W2T  6400   // 64*32 (transposed lin2_w)
#define L_BB2  8448
#define L_G2   8480
#define L_B2   8512

// embedding overlay
#define E_FPW  0      // 32*58
#define E_FPB  1856
#define E_LEMB 1888   // 12*32
#define E_FB   2272   // 3*16

// head overlay
#define H_NOG  0
#define H_NOB  32
#define H_HW   64     // 25*32
#define H_HB   864

#define KV_STRIDE 36
#define OFF_K  8544
#define OFF_V  (OFF_K + WIN*KV_STRIDE)
#define SMEM_FLOATS (OFF_V + WIN*KV_STRIDE)
#define SMEM_BYTES (SMEM_FLOATS * 4)

typedef unsigned long long u64;

__device__ __forceinline__ u64 pk2(float lo, float hi) {
    u64 r; asm("mov.b64 %0,{%1,%2};" : "=l"(r) : "f"(lo), "f"(hi)); return r;
}
__device__ __forceinline__ void upk2(u64 p, float& lo, float& hi) {
    asm("mov.b64 {%0,%1},%2;" : "=f"(lo), "=f"(hi) : "l"(p));
}
__device__ __forceinline__ u64 ffma2(u64 a, u64 b, u64 c) {
    u64 d; asm("fma.rn.f32x2 %0,%1,%2,%3;" : "=l"(d) : "l"(a), "l"(b), "l"(c)); return d;
}
__device__ __forceinline__ u64 fmul2(u64 a, u64 b) {
    u64 d; asm("mul.rn.f32x2 %0,%1,%2;" : "=l"(d) : "l"(a), "l"(b)); return d;
}
__device__ __forceinline__ u64 fadd2(u64 a, u64 b) {
    u64 d; asm("add.rn.f32x2 %0,%1,%2;" : "=l"(d) : "l"(a), "l"(b)); return d;
}
__device__ __forceinline__ float hsum2(u64 p) { float lo, hi; upk2(p, lo, hi); return lo + hi; }
__device__ __forceinline__ u64 dup2(float v) { return pk2(v, v); }
__device__ __forceinline__ float ex2f(float x) {
    float y; asm("ex2.approx.f32 %0,%1;" : "=f"(y) : "f"(x)); return y;
}

// dot of one 32-float weight row against two packed-16 token vectors
__device__ __forceinline__ void dot32x2(const float* __restrict__ w,
                                        const u64  va[16], const u64 vb[16],
                                        float& ra, float& rb) {
    const ulonglong2* wp = reinterpret_cast<const ulonglong2*>(w);
    u64 a0 = 0, a1 = 0, b0 = 0, b1 = 0;
#pragma unroll
    for (int i = 0; i < 8; i++) {
        ulonglong2 wv = wp[i];
        a0 = ffma2(wv.x, va[2 * i], a0);
        a1 = ffma2(wv.y, va[2 * i + 1], a1);
        b0 = ffma2(wv.x, vb[2 * i], b0);
        b1 = ffma2(wv.y, vb[2 * i + 1], b1);
    }
    ra = hsum2(fadd2(a0, a1));
    rb = hsum2(fadd2(b0, b1));
}

// packed layernorm over 16 pairs
__device__ __forceinline__ void ln32p(const u64 v[16], const float* __restrict__ g,
                                      const float* __restrict__ b, u64 o[16]) {
    u64 s = 0;
#pragma unroll
    for (int i = 0; i < 16; i++) s = fadd2(s, v[i]);
    float m = hsum2(s) * 0.03125f;
    u64 mneg = dup2(-m);
    u64 q = 0;
#pragma unroll
    for (int i = 0; i < 16; i++) { u64 d = fadd2(v[i], mneg); o[i] = d; q = ffma2(d, d, q); }
    float var = hsum2(q) * 0.03125f;
    u64 iv = dup2(rsqrtf(var + 1e-5f));
    const ulonglong2* gp = reinterpret_cast<const ulonglong2*>(g);
    const ulonglong2* bp = reinterpret_cast<const ulonglong2*>(b);
#pragma unroll
    for (int i = 0; i < 8; i++) {
        ulonglong2 gg = gp[i], bb = bp[i];
        o[2 * i]     = ffma2(fmul2(o[2 * i], iv), gg.x, bb.x);
        o[2 * i + 1] = ffma2(fmul2(o[2 * i + 1], iv), gg.y, bb.y);
    }
}

__device__ __forceinline__ void embed_token(const float* __restrict__ sw,
                                            const float* __restrict__ xp,
                                            int lay, float h[D_MODEL]) {
    const float p0 = xp[0], p1 = xp[1], p2 = xp[2];
#pragma unroll
    for (int c = 0; c < D_MODEL; c++) h[c] = sw[E_FPB + c] + sw[E_LEMB + lay * 32 + c];
#pragma unroll 1
    for (int k = 0; k < INDIM; k++) {
        float xk = __ldg(xp + k);
#pragma unroll
        for (int c = 0; c < D_MODEL; c++) h[c] = fmaf(xk, sw[E_FPW + c * INDIM + k], h[c]);
    }
#pragma unroll
    for (int j = 0; j < 16; j++) {
        float pr = 6.28318530717958647692f *
                   (p0 * sw[E_FB + j] + p1 * sw[E_FB + 16 + j] + p2 * sw[E_FB + 32 + j]);
        float sn, cs;
        sincosf(pr, &sn, &cs);
        h[j] += sn;
        h[j + 16] += cs;
    }
}

__global__ void __launch_bounds__(128, 2) spai_kernel(
    const float* __restrict__ x, const int* __restrict__ layers,
    const float* __restrict__ fpw, const float* __restrict__ fpb,
    const float* __restrict__ lemb, const float* __restrict__ fB,
    const float* __restrict__ ipw, const float* __restrict__ ipb,
    const float* __restrict__ opw, const float* __restrict__ opb,
    const float* __restrict__ g1, const float* __restrict__ b1,
    const float* __restrict__ w1, const float* __restrict__ bb1,
    const float* __restrict__ w2, const float* __restrict__ bb2,
    const float* __restrict__ g2, const float* __restrict__ b2,
    const float* __restrict__ nog, const float* __restrict__ nob,
    const float* __restrict__ hw, const float* __restrict__ hb,
    float* __restrict__ out)
{
    extern __shared__ float sw[];
    float* ks = sw + OFF_K;
    float* vs = sw + OFF_V;
    const int tid = threadIdx.x;
    const int rowA = 2 * tid, rowB = 2 * tid + 1;         // two token rows per thread
    const long long ga = (long long)blockIdx.x * WIN + rowA;
    const long long gb = ga + 1;

    // ---------------- embedding weights ----------------
    for (int i = tid; i < 32 * INDIM; i += 128) sw[E_FPW + i] = fpw[i];
    if (tid < 32) sw[E_FPB + tid] = fpb[tid];
    for (int i = tid; i < 12 * 32; i += 128) sw[E_LEMB + i] = lemb[i];
    if (tid < 48) sw[E_FB + tid] = fB[tid];
    __syncthreads();

    // ---------------- embedding (2 tokens) ----------------
    float hsa[D_MODEL], hsb[D_MODEL];
    embed_token(sw, x + (size_t)ga * INDIM, layers[ga], hsa);
    embed_token(sw, x + (size_t)gb * INDIM, layers[gb], hsb);

    u64 hA[16], hB[16];
#pragma unroll
    for (int i = 0; i < 16; i++) { hA[i] = pk2(hsa[2 * i], hsa[2 * i + 1]); hB[i] = pk2(hsb[2 * i], hsb[2 * i + 1]); }

    // ---------------- transformer layers ----------------
#pragma unroll 1
    for (int li = 0; li < NLAYER; li++) {
        __syncthreads();
        for (int i = tid; i < 3072; i += 128) sw[L_IPW + i] = ipw[li * 3072 + i];
        if (tid < 96)  sw[L_IPB + tid] = ipb[li * 96 + tid];
        for (int i = tid; i < 1024; i += 128) sw[L_OPW + i] = opw[li * 1024 + i];
        if (tid < 32) {
            sw[L_OPB + tid] = opb[li * 32 + tid];
            sw[L_G1 + tid]  = g1[li * 32 + tid];
            sw[L_B1 + tid]  = b1[li * 32 + tid];
            sw[L_BB2 + tid] = bb2[li * 32 + tid];
            sw[L_G2 + tid]  = g2[li * 32 + tid];
            sw[L_B2 + tid]  = b2[li * 32 + tid];
        }
        for (int i = tid; i < 2048; i += 128) sw[L_W1 + i] = w1[li * 2048 + i];
        if (tid < 64)  sw[L_BB1 + tid] = bb1[li * 64 + tid];
        for (int i = tid; i < 2048; i += 128) {
            int c = i >> 6, f = i & 63;
            sw[L_W2T + f * 32 + c] = w2[li * 2048 + i];
        }
        __syncthreads();

        // ----- QKV -----
        // (1/sqrt(8)) * log2(e) folded into q so softmax uses raw ex2
        const float rs2 = 0.51006464544565f;
        u64 qA[16], qB[16];
#pragma unroll 2
        for (int o = 0; o < 32; o += 2) {
            float a0, b0, a1, b1v;
            dot32x2(sw + L_IPW + o * 32, hA, hB, a0, b0);
            dot32x2(sw + L_IPW + (o + 1) * 32, hA, hB, a1, b1v);
            float i0 = sw[L_IPB + o], i1 = sw[L_IPB + o + 1];
            qA[o >> 1] = pk2((a0 + i0) * rs2, (a1 + i1) * rs2);
            qB[o >> 1] = pk2((b0 + i0) * rs2, (b1v + i1) * rs2);
        }
#pragma unroll 2
        for (int o = 32; o < 96; o += 4) {
            float ta[4], tb[4];
#pragma unroll
            for (int u = 0; u < 4; u++) {
                dot32x2(sw + L_IPW + (o + u) * 32, hA, hB, ta[u], tb[u]);
                float bi = sw[L_IPB + o + u];
                ta[u] += bi; tb[u] += bi;
            }
            float* dst = (o < 64) ? ks : vs;
            int c = (o < 64) ? (o - 32) : (o - 64);
            *reinterpret_cast<float4*>(dst + rowA * KV_STRIDE + c) = make_float4(ta[0], ta[1], ta[2], ta[3]);
            *reinterpret_cast<float4*>(dst + rowB * KV_STRIDE + c) = make_float4(tb[0], tb[1], tb[2], tb[3]);
        }
        __syncthreads();

        // ----- attention (unroll 4: let ptxas batch LDS across iterations) -----
        u64 oaA[16], oaB[16];
#pragma unroll
        for (int i = 0; i < 16; i++) { oaA[i] = 0; oaB[i] = 0; }
        float la[NHEAD] = {0.f, 0.f, 0.f, 0.f};
        float lb[NHEAD] = {0.f, 0.f, 0.f, 0.f};

#pragma unroll 4
        for (int j = 0; j < WIN; j++) {
            const ulonglong2* kp = reinterpret_cast<const ulonglong2*>(ks + j * KV_STRIDE);
            const ulonglong2* vp = reinterpret_cast<const ulonglong2*>(vs + j * KV_STRIDE);
#pragma unroll
            for (int hh = 0; hh < NHEAD; hh++) {
                ulonglong2 kA = kp[2 * hh], kB = kp[2 * hh + 1];
                u64 sa = fmul2(kA.x, qA[4 * hh]);
                sa = ffma2(kA.y, qA[4 * hh + 1], sa);
                sa = ffma2(kB.x, qA[4 * hh + 2], sa);
                sa = ffma2(kB.y, qA[4 * hh + 3], sa);
                u64 sb = fmul2(kA.x, qB[4 * hh]);
                sb = ffma2(kA.y, qB[4 * hh + 1], sb);
                sb = ffma2(kB.x, qB[4 * hh + 2], sb);
                sb = ffma2(kB.y, qB[4 * hh + 3], sb);
                float pa = ex2f(hsum2(sa));
                float pb = ex2f(hsum2(sb));
                la[hh] += pa; lb[hh] += pb;
                u64 ppa = dup2(pa), ppb = dup2(pb);
                ulonglong2 vA = vp[2 * hh], vB = vp[2 * hh + 1];
                oaA[4 * hh]     = ffma2(ppa, vA.x, oaA[4 * hh]);
                oaA[4 * hh + 1] = ffma2(ppa, vA.y, oaA[4 * hh + 1]);
                oaA[4 * hh + 2] = ffma2(ppa, vB.x, oaA[4 * hh + 2]);
                oaA[4 * hh + 3] = ffma2(ppa, vB.y, oaA[4 * hh + 3]);
                oaB[4 * hh]     = ffma2(ppb, vA.x, oaB[4 * hh]);
                oaB[4 * hh + 1] = ffma2(ppb, vA.y, oaB[4 * hh + 1]);
                oaB[4 * hh + 2] = ffma2(ppb, vB.x, oaB[4 * hh + 2]);
                oaB[4 * hh + 3] = ffma2(ppb, vB.y, oaB[4 * hh + 3]);
            }
        }

#pragma unroll
        for (int hh = 0; hh < NHEAD; hh++) {
            u64 rla = dup2(1.0f / la[hh]), rlb = dup2(1.0f / lb[hh]);
#pragma unroll
            for (int p = 0; p < 4; p++) {
                oaA[4 * hh + p] = fmul2(oaA[4 * hh + p], rla);
                oaB[4 * hh + p] = fmul2(oaB[4 * hh + p], rlb);
            }
        }

        // ----- out proj + residual + LN1 -----
        u64 t1a[16], t1b[16];
#pragma unroll 2
        for (int c = 0; c < 32; c += 2) {
            float x0a, x0b, x1a, x1b;
            dot32x2(sw + L_OPW + c * 32, oaA, oaB, x0a, x0b);
            dot32x2(sw + L_OPW + (c + 1) * 32, oaA, oaB, x1a, x1b);
            float o0 = sw[L_OPB + c], o1 = sw[L_OPB + c + 1];
            t1a[c >> 1] = fadd2(hA[c >> 1], pk2(x0a + o0, x1a + o1));
            t1b[c >> 1] = fadd2(hB[c >> 1], pk2(x0b + o0, x1b + o1));
        }
        ln32p(t1a, sw + L_G1, sw + L_B1, hA);
        ln32p(t1b, sw + L_G1, sw + L_B1, hB);

        // ----- FF -----
        u64 f2a[16], f2b[16];
        {
            const ulonglong2* bp = reinterpret_cast<const ulonglong2*>(sw + L_BB2);
#pragma unroll
            for (int i = 0; i < 8; i++) {
                ulonglong2 bb = bp[i];
                f2a[2 * i] = bb.x; f2a[2 * i + 1] = bb.y;
                f2b[2 * i] = bb.x; f2b[2 * i + 1] = bb.y;
            }
        }
#pragma unroll 2
        for (int f = 0; f < DFF; f++) {
            float ta, tb;
            dot32x2(sw + L_W1 + f * 32, hA, hB, ta, tb);
            float bi = sw[L_BB1 + f];
            ta += bi; tb += bi;
            float gla = 0.5f * ta * (1.0f + erff(ta * 0.70710678118654752440f));
            float glb = 0.5f * tb * (1.0f + erff(tb * 0.70710678118654752440f));
            u64 gga = dup2(gla), ggb = dup2(glb);
            const ulonglong2* wp = reinterpret_cast<const ulonglong2*>(sw + L_W2T + f * 32);
#pragma unroll
            for (int i = 0; i < 8; i++) {
                ulonglong2 w2v = wp[i];
                f2a[2 * i]     = ffma2(gga, w2v.x, f2a[2 * i]);
                f2a[2 * i + 1] = ffma2(gga, w2v.y, f2a[2 * i + 1]);
                f2b[2 * i]     = ffma2(ggb, w2v.x, f2b[2 * i]);
                f2b[2 * i + 1] = ffma2(ggb, w2v.y, f2b[2 * i + 1]);
            }
        }
        u64 t2a[16], t2b[16];
#pragma unroll
        for (int i = 0; i < 16; i++) { t2a[i] = fadd2(hA[i], f2a[i]); t2b[i] = fadd2(hB[i], f2b[i]); }
        ln32p(t2a, sw + L_G2, sw + L_B2, hA);
        ln32p(t2b, sw + L_G2, sw + L_B2, hB);
    }

    // ---------------- final LN + head ----------------
    __syncthreads();
    if (tid < 32) { sw[H_NOG + tid] = nog[tid]; sw[H_NOB + tid] = nob[tid]; }
    for (int i = tid; i < HOUT * 32; i += 128) sw[H_HW + i] = hw[i];
    if (tid < HOUT) sw[H_HB + tid] = hb[tid];
    __syncthreads();

    u64 na[16], nb[16];
    ln32p(hA, sw + H_NOG, sw + H_NOB, na);
    ln32p(hB, sw + H_NOG, sw + H_NOB, nb);

    float* outA = out + (size_t)ga * HOUT;
    float* outB = out + (size_t)gb * HOUT;
#pragma unroll 1
    for (int c = 0; c < HOUT; c++) {
        float ta, tb;
        dot32x2(sw + H_HW + c * 32, na, nb, ta, tb);
        float bi = sw[H_HB + c];
        outA[c] = ta + bi;
        outB[c] = tb + bi;
    }
}

extern "C" void kernel_launch(void* const* d_in, const int* in_sizes, int n_in,
                              void* d_out, int out_size) {
    const float* x    = (const float*)d_in[0];
    const int*   lays = (const int*)d_in[1];
    const float* fpw  = (const float*)d_in[2];
    const float* fpb  = (const float*)d_in[3];
    const float* lemb = (const float*)d_in[4];
    const float* fB   = (const float*)d_in[5];
    const float* ipw  = (const float*)d_in[6];
    const float* ipb  = (const float*)d_in[7];
    const float* opw  = (const float*)d_in[8];
    const float* opb  = (const float*)d_in[9];
    const float* g1   = (const float*)d_in[10];
    const float* b1   = (const float*)d_in[11];
    const float* w1   = (const float*)d_in[12];
    const float* bb1  = (const float*)d_in[13];
    const float* w2   = (const float*)d_in[14];
    const float* bb2  = (const float*)d_in[15];
    const float* g2   = (const float*)d_in[16];
    const float* b2   = (const float*)d_in[17];
    const float* nog  = (const float*)d_in[18];
    const float* nob  = (const float*)d_in[19];
    const float* hw   = (const float*)d_in[20];
    const float* hb   = (const float*)d_in[21];
    float* out = (float*)d_out;

    const int tokens = in_sizes[0] / INDIM;
    const int grid = tokens / WIN;

    cudaFuncSetAttribute(spai_kernel, cudaFuncAttributeMaxDynamicSharedMemorySize, SMEM_BYTES);
    spai_kernel<<<grid, 128, SMEM_BYTES>>>(x, lays, fpw, fpb, lemb, fB, ipw, ipb, opw, opb,
                                           g1, b1, w1, bb1, w2, bb2, g2, b2, nog, nob, hw, hb,
                                           out);
}